// round 1
// baseline (speedup 1.0000x reference)
#include <cuda_runtime.h>

#define BATCH 8
#define DIM   128
#define NTOK  32768          // 128*256
#define SPLIT 32
#define CHUNK (NTOK/SPLIT)   // 1024 tokens per k1 block
#define TN    32             // n-tile
#define PAD   132            // smem row pitch (floats), 528B = 16B-aligned

typedef unsigned long long u64;
typedef unsigned int u32;

// ---------------- scratch (no allocations allowed) ----------------
__device__ __align__(16) float g_KVp[BATCH][SPLIT][DIM * DIM];   // 16.8 MB partials
__device__ __align__(16) float g_KV[BATCH][DIM * DIM];
__device__ __align__(16) float g_Ksump[BATCH][SPLIT][DIM];
__device__ __align__(16) float g_Ksum[BATCH][DIM];

// ---------------- packed f32x2 helpers (sm_103a) ----------------
__device__ __forceinline__ u64 pack2(float x, float y) {
    u64 r;
    u32 xi = __float_as_uint(x), yi = __float_as_uint(y);
    asm("mov.b64 %0, {%1, %2};" : "=l"(r) : "r"(xi), "r"(yi));
    return r;
}
__device__ __forceinline__ void fma2(u64& d, u64 a, u64 b) {
    asm("fma.rn.f32x2 %0, %1, %2, %0;" : "+l"(d) : "l"(a), "l"(b));
}
__device__ __forceinline__ u64 mul2(u64 a, u64 b) {
    u64 r;
    asm("mul.rn.f32x2 %0, %1, %2;" : "=l"(r) : "l"(a), "l"(b));
    return r;
}

// phi(x) = elu(x) + 1 = x+1 (x>0) else exp(x)
__device__ __forceinline__ float phi(float x) {
    return x > 0.0f ? x + 1.0f : __expf(x);
}

// ====================================================================
// k1: partial KV[d][e] = sum_n phi(K[d,n]) * V[e,n]  and partial Ksum[d]
// grid (SPLIT, BATCH), 256 threads. 8x8 register tile per thread.
// ====================================================================
__global__ __launch_bounds__(256, 2)
void k1_kv(const float* __restrict__ k, const float* __restrict__ v) {
    const int b = blockIdx.y, s = blockIdx.x;
    const int tid = threadIdx.x;
    const int tx = tid & 15;      // e-tile index (8 cols = 4 pairs)
    const int ty = tid >> 4;      // d-tile index (8 rows)
    const int nf4 = tid & 7;      // loader: float4 index along n
    const int drow = tid >> 3;    // loader: row within 32-row pass

    __shared__ float sk[TN][PAD]; // phi(K), [n][d]
    __shared__ float sv[TN][PAD]; // V,      [n][e]

    u64 acc[8][4];
#pragma unroll
    for (int i = 0; i < 8; i++)
#pragma unroll
        for (int j = 0; j < 4; j++) acc[i][j] = 0ull;

    float ksum_acc[4] = {0.f, 0.f, 0.f, 0.f};

    const float* kb = k + (size_t)b * DIM * NTOK + (size_t)s * CHUNK;
    const float* vb = v + (size_t)b * DIM * NTOK + (size_t)s * CHUNK;

    for (int t0 = 0; t0 < CHUNK; t0 += TN) {
        __syncthreads();
        // load K,V tiles (transpose to [n][d]) — 4 passes of 32 rows
#pragma unroll
        for (int p = 0; p < 4; p++) {
            const int d = p * 32 + drow;
            float4 k4 = *reinterpret_cast<const float4*>(kb + (size_t)d * NTOK + t0 + nf4 * 4);
            float p0 = phi(k4.x), p1 = phi(k4.y), p2 = phi(k4.z), p3 = phi(k4.w);
            ksum_acc[p] += (p0 + p1) + (p2 + p3);
            sk[nf4 * 4 + 0][d] = p0;
            sk[nf4 * 4 + 1][d] = p1;
            sk[nf4 * 4 + 2][d] = p2;
            sk[nf4 * 4 + 3][d] = p3;
            float4 v4 = *reinterpret_cast<const float4*>(vb + (size_t)d * NTOK + t0 + nf4 * 4);
            sv[nf4 * 4 + 0][d] = v4.x;
            sv[nf4 * 4 + 1][d] = v4.y;
            sv[nf4 * 4 + 2][d] = v4.z;
            sv[nf4 * 4 + 3][d] = v4.w;
        }
        __syncthreads();

        for (int j = 0; j < TN; j++) {
            float4 a0 = *reinterpret_cast<const float4*>(&sk[j][ty * 8]);
            float4 a1 = *reinterpret_cast<const float4*>(&sk[j][ty * 8 + 4]);
            ulonglong2 v01 = *reinterpret_cast<const ulonglong2*>(&sv[j][tx * 8]);
            ulonglong2 v23 = *reinterpret_cast<const ulonglong2*>(&sv[j][tx * 8 + 4]);
            u64 ve[4] = {v01.x, v01.y, v23.x, v23.y};
            float kf[8] = {a0.x, a0.y, a0.z, a0.w, a1.x, a1.y, a1.z, a1.w};
#pragma unroll
            for (int i = 0; i < 8; i++) {
                u64 kd = pack2(kf[i], kf[i]);
#pragma unroll
                for (int jj = 0; jj < 4; jj++) fma2(acc[i][jj], kd, ve[jj]);
            }
        }
    }

    // write partial KV (STG.64 of packed pairs)
    float* outp = &g_KVp[b][s][0];
#pragma unroll
    for (int i = 0; i < 8; i++) {
        const int d = ty * 8 + i;
        u64* row = reinterpret_cast<u64*>(outp + d * DIM + tx * 8);
#pragma unroll
        for (int jj = 0; jj < 4; jj++) row[jj] = acc[i][jj];
    }

    // Ksum: 8 consecutive lanes (nf4 0..7) share each d -> shuffle reduce
#pragma unroll
    for (int p = 0; p < 4; p++) {
        float sv_ = ksum_acc[p];
        sv_ += __shfl_down_sync(0xffffffffu, sv_, 4, 8);
        sv_ += __shfl_down_sync(0xffffffffu, sv_, 2, 8);
        sv_ += __shfl_down_sync(0xffffffffu, sv_, 1, 8);
        if (nf4 == 0) g_Ksump[b][s][p * 32 + drow] = sv_;
    }
}

// ====================================================================
// k2: reduce split partials (deterministic, no atomics)
// ====================================================================
__global__ __launch_bounds__(256)
void k2_reduce() {
    const int idx = blockIdx.x * 256 + threadIdx.x; // 0 .. BATCH*DIM*DIM-1
    if (idx < BATCH * DIM * DIM) {
        const int b = idx >> 14;
        const int r = idx & (DIM * DIM - 1);
        float s = 0.f;
#pragma unroll
        for (int p = 0; p < SPLIT; p++) s += g_KVp[b][p][r];
        g_KV[b][r] = s;
    }
    if (idx < BATCH * DIM) {
        const int b = idx >> 7;
        const int d = idx & 127;
        float s = 0.f;
#pragma unroll
        for (int p = 0; p < SPLIT; p++) s += g_Ksump[b][p][d];
        g_Ksum[b][d] = s;
    }
}

// ====================================================================
// k3: out[e][t] = Z[t] * sum_d phi(Q[d,t]) * KV[d][e]
// grid (NTOK/128, BATCH), 256 threads, dyn smem ~131 KB
// ====================================================================
__global__ __launch_bounds__(256, 1)
void k3_out(const float* __restrict__ q, float* __restrict__ out) {
    const int b = blockIdx.y;
    const int t0 = blockIdx.x * 128;
    extern __shared__ float sm[];
    float* kv_s = sm;                       // [128][128]
    float* qp   = sm + DIM * DIM;           // [128][PAD]  phi(Q)
    float* ks   = qp + DIM * PAD;           // [128]
    float* zs   = ks + DIM;                 // [128]

    const int tid = threadIdx.x;
    const int tx = tid & 15;  // t-tile (8 cols = 4 pairs)
    const int ty = tid >> 4;  // e-tile (8 rows)

    // load KV (hot in L2)
    {
        const float4* src = reinterpret_cast<const float4*>(&g_KV[b][0]);
        float4* dst = reinterpret_cast<float4*>(kv_s);
        for (int i = tid; i < DIM * DIM / 4; i += 256) dst[i] = src[i];
    }
    // load Q tile, apply phi
    {
        const float* qb = q + (size_t)b * DIM * NTOK + t0;
        for (int i = tid; i < DIM * 32; i += 256) {
            const int d = i >> 5, c = i & 31;
            float4 x = *reinterpret_cast<const float4*>(qb + (size_t)d * NTOK + c * 4);
            float* row = qp + d * PAD + c * 4;
            row[0] = phi(x.x);
            row[1] = phi(x.y);
            row[2] = phi(x.z);
            row[3] = phi(x.w);
        }
    }
    if (tid < DIM) ks[tid] = g_Ksum[b][tid];
    __syncthreads();

    // Z per token
    if (tid < 128) {
        float s0 = 0.f, s1 = 0.f, s2 = 0.f, s3 = 0.f;
#pragma unroll 8
        for (int d = 0; d < 128; d += 4) {
            s0 += qp[(d + 0) * PAD + tid] * ks[d + 0];
            s1 += qp[(d + 1) * PAD + tid] * ks[d + 1];
            s2 += qp[(d + 2) * PAD + tid] * ks[d + 2];
            s3 += qp[(d + 3) * PAD + tid] * ks[d + 3];
        }
        zs[tid] = 1.0f / (((s0 + s1) + (s2 + s3)) + 1e-8f);
    }
    __syncthreads();

    u64 acc[8][4];
#pragma unroll
    for (int i = 0; i < 8; i++)
#pragma unroll
        for (int j = 0; j < 4; j++) acc[i][j] = 0ull;

    for (int d = 0; d < 128; d++) {
        float4 k0 = *reinterpret_cast<const float4*>(&kv_s[d * DIM + ty * 8]);
        float4 k1 = *reinterpret_cast<const float4*>(&kv_s[d * DIM + ty * 8 + 4]);
        ulonglong2 q01 = *reinterpret_cast<const ulonglong2*>(&qp[d * PAD + tx * 8]);
        ulonglong2 q23 = *reinterpret_cast<const ulonglong2*>(&qp[d * PAD + tx * 8 + 4]);
        u64 qv[4] = {q01.x, q01.y, q23.x, q23.y};
        float kf[8] = {k0.x, k0.y, k0.z, k0.w, k1.x, k1.y, k1.z, k1.w};
#pragma unroll
        for (int i = 0; i < 8; i++) {
            u64 kd = pack2(kf[i], kf[i]);
#pragma unroll
            for (int jj = 0; jj < 4; jj++) fma2(acc[i][jj], kd, qv[jj]);
        }
    }

    // epilogue: scale by z (packed along t), STG.64
    ulonglong2 z01 = *reinterpret_cast<const ulonglong2*>(&zs[tx * 8]);
    ulonglong2 z23 = *reinterpret_cast<const ulonglong2*>(&zs[tx * 8 + 4]);
    u64 zp[4] = {z01.x, z01.y, z23.x, z23.y};
#pragma unroll
    for (int i = 0; i < 8; i++) {
        const int e = ty * 8 + i;
        u64* orow = reinterpret_cast<u64*>(out + ((size_t)b * DIM + e) * NTOK + t0 + tx * 8);
#pragma unroll
        for (int jj = 0; jj < 4; jj++) orow[jj] = mul2(acc[i][jj], zp[jj]);
    }
}

// ====================================================================
extern "C" void kernel_launch(void* const* d_in, const int* in_sizes, int n_in,
                              void* d_out, int out_size) {
    const float* q = (const float*)d_in[0];
    const float* k = (const float*)d_in[1];
    const float* v = (const float*)d_in[2];
    float* out = (float*)d_out;

    const int smem3 = (DIM * DIM + DIM * PAD + DIM + DIM) * (int)sizeof(float); // 134144 B
    cudaFuncSetAttribute(k3_out, cudaFuncAttributeMaxDynamicSharedMemorySize, smem3);

    k1_kv<<<dim3(SPLIT, BATCH), 256>>>(k, v);
    k2_reduce<<<(BATCH * DIM * DIM) / 256, 256>>>();
    k3_out<<<dim3(NTOK / 128, BATCH), 256, smem3>>>(q, out);
}